// round 1
// baseline (speedup 1.0000x reference)
#include <cuda_runtime.h>
#include <cstdint>

#define NQ 4
#define NL 8

// 27 groups (a*9+b*3+c) x 4 floats (d=0..2, pad). Written by setup, read by main.
__device__ __align__(16) float g_T[112];

__device__ __forceinline__ float2 cmul(float2 a, float2 b) {
    return make_float2(a.x * b.x - a.y * b.y, a.x * b.y + a.y * b.x);
}
__device__ __forceinline__ float2 cfma(float2 a, float2 b, float2 acc) {
    acc.x = fmaf(a.x, b.x, fmaf(-a.y, b.y, acc.x));
    acc.y = fmaf(a.x, b.y, fmaf(a.y, b.x, acc.y));
    return acc;
}

// CNOT state-index map: flips target bit if control bit set. Involution.
__device__ __forceinline__ int cnot_map(int m, int c, int t) {
    int bc = 3 - c, bt = 3 - t;
    if ((m >> bc) & 1) m ^= (1 << bt);
    return m;
}

// One block, 256 threads. Builds the 81-coefficient multilinear tensor T from weights.
__global__ void vqc_setup(const float* __restrict__ w) {
    __shared__ float2 sGate[NL * NQ][4];  // 2x2 Rot matrices
    __shared__ float2 sU[256];            // U[col][m] at col*16+m
    __shared__ float2 sM[256];            // per-layer 16x16 single-qubit-layer matrix
    __shared__ float  sG[256];            // real G reindexed by wire pair-codes
    __shared__ float  sA[2][192];         // Tucker ping-pong

    const int t = threadIdx.x;

    // ---- gate matrices ----
    if (t < NL * NQ) {
        float phi = w[t * 3 + 0], th = w[t * 3 + 1], om = w[t * 3 + 2];
        float st, ct; sincosf(0.5f * th, &st, &ct);
        float a = 0.5f * (phi + om), b = 0.5f * (phi - om);
        float sa, ca, sb, cb;
        sincosf(a, &sa, &ca);
        sincosf(b, &sb, &cb);
        sGate[t][0] = make_float2(ca * ct, -sa * ct);   // m00 = e^{-ia} ct
        sGate[t][1] = make_float2(-cb * st, -sb * st);  // m01 = -e^{+ib} st
        sGate[t][2] = make_float2(cb * st, -sb * st);   // m10 = e^{-ib} st
        sGate[t][3] = make_float2(ca * ct, sa * ct);    // m11 = e^{+ia} ct
    }
    // ---- U = identity ----
    {
        int col = t >> 4, m = t & 15;
        sU[t] = make_float2(col == m ? 1.0f : 0.0f, 0.0f);
    }
    __syncthreads();

    // ---- 8 layers: (4 commuting Rot gates as one 16x16 matvec) + (CNOT ring as a permutation) ----
    for (int l = 0; l < NL; l++) {
        // build M[m][n] = prod_w gate_w[m_w][n_w], wire w <-> bit (3-w)
        {
            int m = t >> 4, n = t & 15;
            float2 p = make_float2(1.0f, 0.0f);
#pragma unroll
            for (int wq = 0; wq < 4; wq++) {
                int bi = 3 - wq;
                float2 g = sGate[l * 4 + wq][((m >> bi) & 1) * 2 + ((n >> bi) & 1)];
                p = cmul(p, g);
            }
            sM[t] = p;
        }
        __syncthreads();
        // matvec: new U[col][m] = sum_n M[m][n] U[col][n]
        float2 acc = make_float2(0.0f, 0.0f);
        {
            int col = t >> 4, m = t & 15;
#pragma unroll
            for (int n = 0; n < 16; n++)
                acc = cfma(sM[m * 16 + n], sU[col * 16 + n], acc);
        }
        __syncthreads();
        sU[t] = acc;
        __syncthreads();
        // CNOT block: sigma = c30 o c23 o c12 o c01 (c01 applied first);
        // new[m] = old[sigma^{-1}(m)], sigma^{-1}(m) = c01(c12(c23(c30(m))))
        {
            int col = t >> 4, m = t & 15;
            int src = m;
            src = cnot_map(src, 3, 0);
            src = cnot_map(src, 2, 3);
            src = cnot_map(src, 1, 2);
            src = cnot_map(src, 0, 1);
            float2 v = sU[col * 16 + src];
            __syncthreads();
            sU[t] = v;
        }
        __syncthreads();
    }

    // ---- H = U^dag Z0 U, phase-fold to real G, store indexed by per-wire pair code ----
    {
        int j = t >> 4, k = t & 15;
        float hr = 0.0f, hi = 0.0f;
#pragma unroll
        for (int m = 0; m < 16; m++) {
            float zz = ((m >> 3) & 1) ? -1.0f : 1.0f;
            float2 uj = sU[j * 16 + m], uk = sU[k * 16 + m];
            hr += zz * (uj.x * uk.x + uj.y * uk.y);
            hi += zz * (uj.x * uk.y - uj.y * uk.x);
        }
        int q = (__popc(j) - __popc(k)) & 3;  // i^q * H, take Re
        float gval = (q == 0) ? hr : (q == 1) ? -hi : (q == 2) ? -hr : hi;
        int gidx = 0;
#pragma unroll
        for (int wq = 0; wq < 4; wq++) {
            int bi = 3 - wq;
            int p = ((j >> bi) & 1) * 2 + ((k >> bi) & 1);
            gidx = gidx * 4 + p;
        }
        sG[gidx] = gval;
    }
    __syncthreads();

    // ---- Tucker: contract each wire's pair-code (4) with V (4x3) -> T (3^4) ----
    // pair code 0:(0,0)->c^2, 1:(0,1)->cs, 2:(1,0)->cs, 3:(1,1)->s^2, expressed in (1, cos x, sin x)
    const float V[4][3] = {{0.5f, 0.5f, 0.0f},
                           {0.0f, 0.0f, 0.5f},
                           {0.0f, 0.0f, 0.5f},
                           {0.5f, -0.5f, 0.0f}};
    float* A1 = sA[0];
    float* A2 = sA[1];
    if (t < 192) {  // A1[p0][p1][p2][d] ; t = ((p0*4+p1)*4+p2)*3+d
        int d = t % 3, p2 = (t / 3) & 3, p1 = (t / 12) & 3, p0 = t / 48;
        float acc = 0.0f;
#pragma unroll
        for (int p3 = 0; p3 < 4; p3++)
            acc += sG[((p0 * 4 + p1) * 4 + p2) * 4 + p3] * V[p3][d];
        A1[t] = acc;
    }
    __syncthreads();
    if (t < 144) {  // A2[p0][p1][c][d] ; t = ((p0*4+p1)*3+c)*3+d
        int d = t % 3, c = (t / 3) % 3, rest = t / 9;
        int p1 = rest & 3, p0 = rest >> 2;
        float acc = 0.0f;
#pragma unroll
        for (int p2 = 0; p2 < 4; p2++)
            acc += A1[((p0 * 4 + p1) * 4 + p2) * 3 + d] * V[p2][c];
        A2[t] = acc;
    }
    __syncthreads();
    if (t < 108) {  // A3[p0][b][c][d] (reuse A1) ; t = ((p0*3+b)*3+c)*3+d
        int d = t % 3, c = (t / 3) % 3, b = (t / 9) % 3, p0 = t / 27;
        float acc = 0.0f;
#pragma unroll
        for (int p1 = 0; p1 < 4; p1++)
            acc += A2[((p0 * 4 + p1) * 3 + c) * 3 + d] * V[p1][b];
        A1[t] = acc;
    }
    __syncthreads();
    if (t < 81) {  // T[a][b][c][d] -> g_T[(a*9+b*3+c)*4 + d]
        int d = t % 3, c = (t / 3) % 3, b = (t / 9) % 3, a = t / 27;
        float acc = 0.0f;
#pragma unroll
        for (int p0 = 0; p0 < 4; p0++)
            acc += A1[((p0 * 3 + b) * 3 + c) * 3 + d] * V[p0][a];
        g_T[(a * 9 + b * 3 + c) * 4 + d] = acc;
    } else if (t < 108) {
        g_T[(t - 81) * 4 + 3] = 0.0f;  // pad lanes
    }
}

// Per-sample: E = sum_{a,b,c,d} T[a,b,c,d] f0[a] f1[b] f2[c] f3[d], f = (1, cos x, sin x)
__global__ void __launch_bounds__(256) vqc_main(const float4* __restrict__ x,
                                               float* __restrict__ out, int n) {
    __shared__ float4 sT[28];
    if (threadIdx.x < 28) sT[threadIdx.x] = reinterpret_cast<const float4*>(g_T)[threadIdx.x];
    __syncthreads();

    int i = blockIdx.x * 256 + threadIdx.x;
    if (i >= n) return;

    float4 xv = x[i];
    float s0, c0, s1, c1, s2, c2, s3, c3;
    __sincosf(xv.x, &s0, &c0);
    __sincosf(xv.y, &s1, &c1);
    __sincosf(xv.z, &s2, &c2);
    __sincosf(xv.w, &s3, &c3);

    float r9[9];
#pragma unroll
    for (int u = 0; u < 9; u++) {  // u = a*3 + b ; contract wires 3 then 2
        float4 t0 = sT[u * 3 + 0];
        float4 t1 = sT[u * 3 + 1];
        float4 t2 = sT[u * 3 + 2];
        float a0 = fmaf(t0.z, s3, fmaf(t0.y, c3, t0.x));
        float a1 = fmaf(t1.z, s3, fmaf(t1.y, c3, t1.x));
        float a2 = fmaf(t2.z, s3, fmaf(t2.y, c3, t2.x));
        r9[u] = fmaf(a2, s2, fmaf(a1, c2, a0));
    }
    float b0 = fmaf(r9[2], s1, fmaf(r9[1], c1, r9[0]));
    float b1 = fmaf(r9[5], s1, fmaf(r9[4], c1, r9[3]));
    float b2 = fmaf(r9[8], s1, fmaf(r9[7], c1, r9[6]));
    out[i] = fmaf(b2, s0, fmaf(b1, c0, b0));
}

extern "C" void kernel_launch(void* const* d_in, const int* in_sizes, int n_in,
                              void* d_out, int out_size) {
    const float* x = (const float*)d_in[0];        // (B, 4)
    const float* w = (const float*)d_in[1];        // (8, 4, 3)
    float* out = (float*)d_out;                    // (B,)
    int n = out_size;                              // B

    vqc_setup<<<1, 256>>>(w);
    vqc_main<<<(n + 255) / 256, 256>>>((const float4*)x, out, n);
}

// round 3
// speedup vs baseline: 1.8341x; 1.8341x over previous
#include <cuda_runtime.h>
#include <cstdint>

#define NQ 4
#define NL 8

// 27 groups (a*9+b*3+c) x 4 floats (d=0..2, pad). Written by setup, read by main.
__device__ __align__(16) float g_T[112];

__device__ __forceinline__ float2 cmul(float2 a, float2 b) {
    return make_float2(fmaf(a.x, b.x, -a.y * b.y), fmaf(a.x, b.y, a.y * b.x));
}
__device__ __forceinline__ float2 cfma(float2 a, float2 b, float2 acc) {
    acc.x = fmaf(a.x, b.x, fmaf(-a.y, b.y, acc.x));
    acc.y = fmaf(a.x, b.y, fmaf(a.y, b.x, acc.y));
    return acc;
}

// CNOT state-index map: flips target bit if control bit set. Involution.
__device__ __forceinline__ int cnot_map(int m, int c, int t) {
    int bc = 3 - c, bt = 3 - t;
    if ((m >> bc) & 1) m ^= (1 << bt);
    return m;
}

// One block, 256 threads. Builds the 81-coefficient multilinear tensor T from weights.
// All per-layer wire-pair Kronecker products precomputed (1 entry/thread),
// CNOT permutation folded into the matvec write, ping-pong buffers -> 1 sync/layer.
__global__ void vqc_setup(const float* __restrict__ w) {
    __shared__ float2 sGate[NL * NQ][4];   // 2x2 Rot matrices
    __shared__ float2 sPA[NL][16];         // g(w0) (x) g(w1), per layer
    __shared__ float2 sPB[NL][16];         // g(w2) (x) g(w3), per layer
    __shared__ float2 sUa[256], sUb[256];  // U[col][m] ping-pong
    __shared__ float  sG[256];             // real G reindexed by wire pair-codes
    __shared__ float  sA1[192], sA2[144];  // Tucker staging

    const int t = threadIdx.x;

    // ---- phase 0: gate matrices (t<32) + identity init ----
    if (t < NL * NQ) {
        float phi = w[t * 3 + 0], th = w[t * 3 + 1], om = w[t * 3 + 2];
        float st, ct; __sincosf(0.5f * th, &st, &ct);
        float a = 0.5f * (phi + om), b = 0.5f * (phi - om);
        float sa, ca, sb, cb;
        __sincosf(a, &sa, &ca);
        __sincosf(b, &sb, &cb);
        sGate[t][0] = make_float2(ca * ct, -sa * ct);   // m00 = e^{-ia} ct
        sGate[t][1] = make_float2(-cb * st, -sb * st);  // m01 = -e^{+ib} st
        sGate[t][2] = make_float2(cb * st, -sb * st);   // m10 = e^{-ib} st
        sGate[t][3] = make_float2(ca * ct, sa * ct);    // m11 = e^{+ia} ct
    }
    {
        int col = t >> 4, m = t & 15;
        sUa[t] = make_float2(col == m ? 1.0f : 0.0f, 0.0f);
    }
    __syncthreads();

    // ---- phase 1: pair Kronecker factors, one entry per thread ----
    // Row index m: wire w <-> bit (3-w). m>>2 = (m0,m1) wires 0,1 ; m&3 = (m2,m3).
    {
        int l = t >> 5, r = t & 31;
        int which = r >> 4, idx = r & 15;
        int i = idx >> 2, j = idx & 3;
        const float2* gA = sGate[l * 4 + which * 2 + 0];  // wire 0 (PA) or 2 (PB)
        const float2* gB = sGate[l * 4 + which * 2 + 1];  // wire 1 (PA) or 3 (PB)
        float2 v = cmul(gA[(i >> 1) * 2 + (j >> 1)], gB[(i & 1) * 2 + (j & 1)]);
        if (which) sPB[l][idx] = v; else sPA[l][idx] = v;
    }
    __syncthreads();

    // ---- phase 2: 8 layers, 1 sync each ----
    // new U[col][sigma(m)] = sum_n M[m][n] U[col][n],
    // M[m][n] = PA[m>>2][n>>2] * PB[m&3][n&3],
    // sigma = c30 o c23 o c12 o c01 (c01 applied first).
    float2* cur = sUa;
    float2* nxt = sUb;
    const int col = t >> 4, m = t & 15;
    const int mh = m >> 2, ml = m & 3;
    int mp = m;
    mp = cnot_map(mp, 0, 1);
    mp = cnot_map(mp, 1, 2);
    mp = cnot_map(mp, 2, 3);
    mp = cnot_map(mp, 3, 0);
    for (int l = 0; l < NL; l++) {
        float2 acc = make_float2(0.0f, 0.0f);
#pragma unroll
        for (int nh = 0; nh < 4; nh++) {
            float2 inner = make_float2(0.0f, 0.0f);
#pragma unroll
            for (int nl = 0; nl < 4; nl++)
                inner = cfma(sPB[l][ml * 4 + nl], cur[col * 16 + nh * 4 + nl], inner);
            acc = cfma(sPA[l][mh * 4 + nh], inner, acc);
        }
        nxt[col * 16 + mp] = acc;
        __syncthreads();
        float2* tmp = cur; cur = nxt; nxt = tmp;
    }

    // ---- phase 3: H = U^dag Z0 U, phase-fold to real G ----
    {
        int j = t >> 4, k = t & 15;
        float hr = 0.0f, hi = 0.0f;
#pragma unroll
        for (int mm = 0; mm < 16; mm++) {
            float zz = ((mm >> 3) & 1) ? -1.0f : 1.0f;
            float2 uj = cur[j * 16 + mm], uk = cur[k * 16 + mm];
            hr += zz * (uj.x * uk.x + uj.y * uk.y);
            hi += zz * (uj.x * uk.y - uj.y * uk.x);
        }
        int q = (__popc(j) - __popc(k)) & 3;  // i^q * H, take Re
        float gval = (q == 0) ? hr : (q == 1) ? -hi : (q == 2) ? -hr : hi;
        int gidx = 0;
#pragma unroll
        for (int wq = 0; wq < 4; wq++) {
            int bi = 3 - wq;
            int p = ((j >> bi) & 1) * 2 + ((k >> bi) & 1);
            gidx = gidx * 4 + p;
        }
        sG[gidx] = gval;
    }
    __syncthreads();

    // ---- phase 4: Tucker contract each wire's pair-code (4) with V (4x3) ----
    // pair code 0:(0,0)->c^2, 1:(0,1)->cs, 2:(1,0)->cs, 3:(1,1)->s^2 in (1, cos x, sin x)
    const float V[4][3] = {{0.5f, 0.5f, 0.0f},
                           {0.0f, 0.0f, 0.5f},
                           {0.0f, 0.0f, 0.5f},
                           {0.5f, -0.5f, 0.0f}};
    if (t < 192) {  // A1[p0][p1][p2][d]
        int d = t % 3, p2 = (t / 3) & 3, p1 = (t / 12) & 3, p0 = t / 48;
        float acc = 0.0f;
#pragma unroll
        for (int p3 = 0; p3 < 4; p3++)
            acc += sG[((p0 * 4 + p1) * 4 + p2) * 4 + p3] * V[p3][d];
        sA1[t] = acc;
    }
    __syncthreads();
    if (t < 144) {  // A2[p0][p1][c][d]
        int d = t % 3, c = (t / 3) % 3, rest = t / 9;
        int p1 = rest & 3, p0 = rest >> 2;
        float acc = 0.0f;
#pragma unroll
        for (int p2 = 0; p2 < 4; p2++)
            acc += sA1[((p0 * 4 + p1) * 4 + p2) * 3 + d] * V[p2][c];
        sA2[t] = acc;
    }
    __syncthreads();
    if (t < 108) {  // A3[p0][b][c][d] (reuse sA1)
        int d = t % 3, c = (t / 3) % 3, b = (t / 9) % 3, p0 = t / 27;
        float acc = 0.0f;
#pragma unroll
        for (int p1 = 0; p1 < 4; p1++)
            acc += sA2[((p0 * 4 + p1) * 3 + c) * 3 + d] * V[p1][b];
        sA1[t] = acc;
    }
    __syncthreads();
    if (t < 81) {  // T[a][b][c][d] -> g_T[(a*9+b*3+c)*4 + d]
        int d = t % 3, c = (t / 3) % 3, b = (t / 9) % 3, a = t / 27;
        float acc = 0.0f;
#pragma unroll
        for (int p0 = 0; p0 < 4; p0++)
            acc += sA1[((p0 * 3 + b) * 3 + c) * 3 + d] * V[p0][a];
        g_T[(a * 9 + b * 3 + c) * 4 + d] = acc;
    } else if (t < 108) {
        g_T[(t - 81) * 4 + 3] = 0.0f;  // pad lanes
    }
}

// Per-sample: E = sum T[a,b,c,d] f0[a] f1[b] f2[c] f3[d], f = (1, cos x, sin x).
// 4 samples per thread: amortizes the 27 float4 sT loads (LDS was the R1 wall).
#define SPT 4
__global__ void __launch_bounds__(256) vqc_main(const float4* __restrict__ x,
                                                float* __restrict__ out, int n) {
    __shared__ float4 sT[28];
    if (threadIdx.x < 28) sT[threadIdx.x] = reinterpret_cast<const float4*>(g_T)[threadIdx.x];
    __syncthreads();

    const int base = blockIdx.x * (256 * SPT) + threadIdx.x;

    float x0[SPT], x1[SPT];
    float s2v[SPT], c2v[SPT], s3v[SPT], c3v[SPT];
#pragma unroll
    for (int k = 0; k < SPT; k++) {
        int i = base + k * 256;
        float4 xv = (i < n) ? x[i] : make_float4(0.0f, 0.0f, 0.0f, 0.0f);
        x0[k] = xv.x; x1[k] = xv.y;
        __sincosf(xv.z, &s2v[k], &c2v[k]);
        __sincosf(xv.w, &s3v[k], &c3v[k]);
    }

    float r9[SPT][9];
#pragma unroll
    for (int u = 0; u < 9; u++) {  // u = a*3 + b ; contract wires 3 then 2
        float4 t0 = sT[u * 3 + 0];
        float4 t1 = sT[u * 3 + 1];
        float4 t2 = sT[u * 3 + 2];
#pragma unroll
        for (int k = 0; k < SPT; k++) {
            float a0 = fmaf(t0.z, s3v[k], fmaf(t0.y, c3v[k], t0.x));
            float a1 = fmaf(t1.z, s3v[k], fmaf(t1.y, c3v[k], t1.x));
            float a2 = fmaf(t2.z, s3v[k], fmaf(t2.y, c3v[k], t2.x));
            r9[k][u] = fmaf(a2, s2v[k], fmaf(a1, c2v[k], a0));
        }
    }

#pragma unroll
    for (int k = 0; k < SPT; k++) {
        float s0, c0, s1, c1;
        __sincosf(x0[k], &s0, &c0);
        __sincosf(x1[k], &s1, &c1);
        float b0 = fmaf(r9[k][2], s1, fmaf(r9[k][1], c1, r9[k][0]));
        float b1 = fmaf(r9[k][5], s1, fmaf(r9[k][4], c1, r9[k][3]));
        float b2 = fmaf(r9[k][8], s1, fmaf(r9[k][7], c1, r9[k][6]));
        int i = base + k * 256;
        if (i < n) out[i] = fmaf(b2, s0, fmaf(b1, c0, b0));
    }
}

extern "C" void kernel_launch(void* const* d_in, const int* in_sizes, int n_in,
                              void* d_out, int out_size) {
    const float* x = (const float*)d_in[0];        // (B, 4)
    const float* w = (const float*)d_in[1];        // (8, 4, 3)
    float* out = (float*)d_out;                    // (B,)
    int n = out_size;                              // B

    vqc_setup<<<1, 256>>>(w);
    int per_block = 256 * SPT;
    vqc_main<<<(n + per_block - 1) / per_block, 256>>>((const float4*)x, out, n);
}